// round 16
// baseline (speedup 1.0000x reference)
#include <cuda_runtime.h>
#include <cstdint>

// ---------------------------------------------------------------------------
// Model_78898549227585: embed -> GRU encoder (T=5) -> GATConv -> GRUCell
// decoder (T_OUT=6, autoregressive) + confidence head.
// B=32768, T=5, N=5, H=64, F=10, M=5.
// fp32x2-packed gate math; 512-thread blocks, 1 node/thread (4 warps/SMSP for
// latency hiding), persistent tiles; h bounced through smem (static regs only).
// ---------------------------------------------------------------------------

#define DINL __device__ __forceinline__

typedef unsigned long long u64;

constexpr int Bq   = 32768;
constexpr int Tq   = 5;
constexpr int Nq   = 5;
constexpr int Fq   = 10;
constexpr int Hq   = 64;
constexpr int Gq   = 192;   // 3H
constexpr int Mq   = 5;
constexpr int TOq  = 6;
constexpr int BNq  = Bq * Nq;                       // 163840
constexpr int TILES = BNq / 512;                    // 320
constexpr int GRID  = 296;                          // 2 * 148 SMs
constexpr long long TRAJ_ELEMS = (long long)Bq * Mq * Nq * TOq * 2;  // 9,830,400

// ------------------------- device scratch ---------------------------------
__device__ float g_Wc_enc[Gq * Fq];
__device__ float g_bc_enc[Gq];
__device__ float g_Wc_dec[Gq * 2];
__device__ float g_bc_dec[Gq];
__device__ float g_Wc_xl[Fq * Hq];
__device__ float g_b_xl[Hq];

__device__ __align__(16) float g_henc[(size_t)BNq * Hq];
__device__ __align__(16) float g_xl  [(size_t)BNq * Hq];
__device__ float g_as  [BNq];
__device__ float g_ad  [BNq];
__device__ int   g_mask[BNq];
__device__ __align__(16) float g_hfin[(size_t)BNq * Hq];

// ------------------------- packed helpers ----------------------------------
DINL u64 fma2(u64 a, u64 b, u64 c) {
    u64 d; asm("fma.rn.f32x2 %0,%1,%2,%3;" : "=l"(d) : "l"(a), "l"(b), "l"(c));
    return d;
}
DINL u64 add2(u64 a, u64 b) {
    u64 d; asm("add.rn.f32x2 %0,%1,%2;" : "=l"(d) : "l"(a), "l"(b));
    return d;
}
DINL float2 unpk(u64 v) {
    float2 f; asm("mov.b64 {%0,%1},%2;" : "=f"(f.x), "=f"(f.y) : "l"(v));
    return f;
}
DINL u64 pk(float lo, float hi) {
    u64 v; asm("mov.b64 %0,{%1,%2};" : "=l"(v) : "f"(lo), "f"(hi));
    return v;
}
DINL float hadd(u64 v) { float2 f = unpk(v); return f.x + f.y; }
DINL u64 bc2(float x)  { return pk(x, x); }

DINL float sigmf(float v)  { return __fdividef(1.f, 1.f + __expf(-v)); }
DINL float tanhf_(float v) { return 1.f - __fdividef(2.f, __expf(2.f * v) + 1.f); }

// ------------------------- prep: fold weights ------------------------------
__global__ void prep_kernel(const float* __restrict__ enc_Wih,
                            const float* __restrict__ enc_bih,
                            const float* __restrict__ dec_Wih,
                            const float* __restrict__ dec_bih,
                            const float* __restrict__ embW,
                            const float* __restrict__ embB,
                            const float* __restrict__ projW,
                            const float* __restrict__ projB,
                            const float* __restrict__ gatW)
{
    int t = blockIdx.x * blockDim.x + threadIdx.x;
    if (t < Gq * Fq) {
        int j = t / Fq, c = t % Fq;
        float s = 0.f;
        for (int k = 0; k < Hq; k++) s += enc_Wih[j * Hq + k] * embW[c * Hq + k];
        g_Wc_enc[j * Fq + c] = s;
    } else if (t < 1920 + 192) {
        int j = t - 1920;
        float s = enc_bih[j];
        for (int k = 0; k < Hq; k++) s += enc_Wih[j * Hq + k] * embB[k];
        g_bc_enc[j] = s;
    } else if (t < 2112 + 384) {
        int i = t - 2112;
        int j = i / 2, c = i % 2;
        float s = 0.f;
        for (int k = 0; k < Hq; k++) s += dec_Wih[j * Hq + k] * projW[c * Hq + k];
        g_Wc_dec[j * 2 + c] = s;
    } else if (t < 2496 + 192) {
        int j = t - 2496;
        float s = dec_bih[j];
        for (int k = 0; k < Hq; k++) s += dec_Wih[j * Hq + k] * projB[k];
        g_bc_dec[j] = s;
    } else if (t < 2688 + 640) {
        int i = t - 2688;
        int c = i / Hq, k2 = i % Hq;
        float s = 0.f;
        for (int k = 0; k < Hq; k++) s += embW[c * Hq + k] * gatW[k * Hq + k2];
        g_Wc_xl[c * Hq + k2] = s;
    } else if (t < 3328 + 64) {
        int k2 = t - 3328;
        float s = 0.f;
        for (int k = 0; k < Hq; k++) s += embB[k] * gatW[k * Hq + k2];
        g_b_xl[k2] = s;
    }
}

// ------------------------- encoder ------------------------------------------
// 512 threads, 1 node/thread, persistent over tiles of 512 nodes.
// smem floats:
//  sWhh 12288 | sBhh 192 | sWc 2304 (stride 12) | sBc 192 | sWxl 640 |
//  sBxl 64 | sAs 64 | sAd 64 | hs 32*512 u64
constexpr int E_WHH = 0;
constexpr int E_BHH = 12288;
constexpr int E_WC  = 12480;
constexpr int E_BC  = 14784;
constexpr int E_WXL = 14976;
constexpr int E_BXL = 15616;
constexpr int E_AS  = 15680;
constexpr int E_AD  = 15744;
constexpr int E_HS  = 15808;
constexpr int ENC_SMEM_FLOATS = E_HS + 32 * 512 * 2;   // 48576
constexpr int ENC_SMEM_BYTES  = ENC_SMEM_FLOATS * 4;   // 194304

// encoder epilogue for one node
DINL void enc_epi(int bn, const u64* xq, const u64* h2,
                  const float* sWxl, const float* sBxl,
                  const float* sAs, const float* sAd)
{
    u64* ghe = reinterpret_cast<u64*>(g_henc) + (size_t)bn * 32;
    #pragma unroll
    for (int k = 0; k < 32; k++) ghe[k] = h2[k];

    float x10[10];
    #pragma unroll
    for (int c2 = 0; c2 < 5; c2++) {
        float2 v = unpk(xq[c2]);
        x10[2 * c2] = v.x; x10[2 * c2 + 1] = v.y;
    }
    float s6 = x10[0] + x10[1] + x10[2] + x10[3] + x10[4] + x10[5];
    g_mask[bn] = (s6 != 0.f) ? 1 : 0;

    u64 xb[10];
    #pragma unroll
    for (int c = 0; c < 10; c++) xb[c] = bc2(x10[c]);
    const u64* bxl2 = (const u64*)sBxl;
    const u64* asp  = (const u64*)sAs;
    const u64* adp  = (const u64*)sAd;
    u64* gxl = reinterpret_cast<u64*>(g_xl) + (size_t)bn * 32;
    u64 asum = 0, adsum = 0;
    #pragma unroll 2
    for (int k2 = 0; k2 < 32; k2++) {
        u64 acc = bxl2[k2];
        #pragma unroll
        for (int c = 0; c < 10; c++)
            acc = fma2(xb[c], *((const u64*)(sWxl + c * 64) + k2), acc);
        gxl[k2] = acc;
        asum  = fma2(acc, asp[k2], asum);
        adsum = fma2(acc, adp[k2], adsum);
    }
    g_as[bn] = hadd(asum);
    g_ad[bn] = hadd(adsum);
}

__global__ void __launch_bounds__(512, 1) enc_kernel(
    const float* __restrict__ x,
    const float* __restrict__ Whh,
    const float* __restrict__ bhh,
    const float* __restrict__ asrc,
    const float* __restrict__ adst)
{
    extern __shared__ float sm[];
    float* sWhh = sm + E_WHH;
    float* sBhh = sm + E_BHH;
    float* sWc  = sm + E_WC;
    float* sBc  = sm + E_BC;
    float* sWxl = sm + E_WXL;
    float* sBxl = sm + E_BXL;
    float* sAs  = sm + E_AS;
    float* sAd  = sm + E_AD;
    u64*   hsu  = reinterpret_cast<u64*>(sm + E_HS);

    const int tid = threadIdx.x;
    for (int i = tid; i < 12288; i += 512) sWhh[i] = Whh[i];
    for (int i = tid; i < 2304;  i += 512) {
        int j = i / 12, c = i % 12;
        sWc[i] = (c < 10) ? g_Wc_enc[j * 10 + c] : 0.f;
    }
    for (int i = tid; i < 640;   i += 512) sWxl[i] = g_Wc_xl[i];
    if (tid < 192) { sBhh[tid] = bhh[tid]; sBc[tid] = g_bc_enc[tid]; }
    if (tid < 64) { sBxl[tid] = g_b_xl[tid]; sAs[tid] = asrc[tid]; sAd[tid] = adst[tid]; }
    __syncthreads();

    for (int tile = blockIdx.x; tile < TILES; tile += GRID) {

    const int bn = tile * 512 + tid;
    const float* xp = x + ((size_t)(bn / Nq) * (Tq * Nq) + (bn % Nq)) * Fq;

    u64 h2[32];
    #pragma unroll
    for (int k = 0; k < 32; k++) { h2[k] = 0ULL; hsu[k * 512 + tid] = 0ULL; }

    u64 xq[5];

    for (int t = 0; t < Tq; t++) {
        {
            const float2* a2 = reinterpret_cast<const float2*>(xp + (size_t)t * (Nq * Fq));
            #pragma unroll
            for (int c2 = 0; c2 < 5; c2++) {
                float2 v = a2[c2]; xq[c2] = pk(v.x, v.y);
            }
        }

        #pragma unroll 1
        for (int jj = 0; jj < 32; jj++) {
            const int j = 2 * jj;
            const ulonglong2* wh0 = (const ulonglong2*)(sWhh + j * 64);
            const ulonglong2* wh1 = (const ulonglong2*)(sWhh + (j + 1) * 64);
            const ulonglong2* wh2 = (const ulonglong2*)(sWhh + (j + 64) * 64);
            const ulonglong2* wh3 = (const ulonglong2*)(sWhh + (j + 65) * 64);
            const ulonglong2* wh4 = (const ulonglong2*)(sWhh + (j + 128) * 64);
            const ulonglong2* wh5 = (const ulonglong2*)(sWhh + (j + 129) * 64);
            u64 r0 = 0, r1 = 0, z0 = 0, z1 = 0, n0 = 0, n1 = 0;
            #pragma unroll
            for (int k4 = 0; k4 < 16; k4++) {
                u64 ha = h2[2 * k4], hb = h2[2 * k4 + 1];
                ulonglong2 w;
                w = wh0[k4]; r0 = fma2(w.x, ha, r0); r0 = fma2(w.y, hb, r0);
                w = wh1[k4]; r1 = fma2(w.x, ha, r1); r1 = fma2(w.y, hb, r1);
                w = wh2[k4]; z0 = fma2(w.x, ha, z0); z0 = fma2(w.y, hb, z0);
                w = wh3[k4]; z1 = fma2(w.x, ha, z1); z1 = fma2(w.y, hb, z1);
                w = wh4[k4]; n0 = fma2(w.x, ha, n0); n0 = fma2(w.y, hb, n0);
                w = wh5[k4]; n1 = fma2(w.x, ha, n1); n1 = fma2(w.y, hb, n1);
            }
            const u64* cx0 = (const u64*)(sWc + j * 12);
            const u64* cx1 = (const u64*)(sWc + (j + 1) * 12);
            const u64* cx2 = (const u64*)(sWc + (j + 64) * 12);
            const u64* cx3 = (const u64*)(sWc + (j + 65) * 12);
            const u64* cx4 = (const u64*)(sWc + (j + 128) * 12);
            const u64* cx5 = (const u64*)(sWc + (j + 129) * 12);
            u64 xn0 = 0, xn1 = 0;
            #pragma unroll
            for (int c2 = 0; c2 < 5; c2++) {
                u64 xv = xq[c2];
                r0  = fma2(cx0[c2], xv, r0);
                r1  = fma2(cx1[c2], xv, r1);
                z0  = fma2(cx2[c2], xv, z0);
                z1  = fma2(cx3[c2], xv, z1);
                xn0 = fma2(cx4[c2], xv, xn0);
                xn1 = fma2(cx5[c2], xv, xn1);
            }
            float R0 = sigmf(hadd(r0) + sBhh[j]      + sBc[j]);
            float R1 = sigmf(hadd(r1) + sBhh[j + 1]  + sBc[j + 1]);
            float Z0 = sigmf(hadd(z0) + sBhh[j + 64] + sBc[j + 64]);
            float Z1 = sigmf(hadd(z1) + sBhh[j + 65] + sBc[j + 65]);
            float N0 = tanhf_(hadd(xn0) + sBc[j + 128] + R0 * (hadd(n0) + sBhh[j + 128]));
            float N1 = tanhf_(hadd(xn1) + sBc[j + 129] + R1 * (hadd(n1) + sBhh[j + 129]));
            float2 ho = unpk(h2[jj]);
            hsu[jj * 512 + tid] = pk((1.f - Z0) * N0 + Z0 * ho.x,
                                     (1.f - Z1) * N1 + Z1 * ho.y);
        }
        #pragma unroll
        for (int k = 0; k < 32; k++) h2[k] = hsu[k * 512 + tid];
    }

    enc_epi(bn, xq, h2, sWxl, sBxl, sAs, sAd);

    }   // tile loop
}

// ------------------------- GAT + conf ---------------------------------------
__global__ void __launch_bounds__(128) gat_kernel(
    const float* __restrict__ gat_b,
    const float* __restrict__ cW1,
    const float* __restrict__ cB1,
    const float* __restrict__ cW2,
    const float* __restrict__ cB2,
    float* __restrict__ out)
{
    __shared__ __align__(16) float sW1t[4096];   // [m][k]
    __shared__ __align__(16) float sB1[64];
    __shared__ __align__(16) float sW2[512];     // [m][p] padded stride 8
    __shared__ __align__(16) float sB2[8];
    __shared__ __align__(16) float sGb[64];

    const int tid = threadIdx.x;
    for (int i = tid; i < 4096; i += 128) {
        int m = i >> 6, k = i & 63;
        sW1t[i] = cW1[k * 64 + m];
    }
    for (int i = tid; i < 512; i += 128) {
        int m = i >> 3, p = i & 7;
        sW2[i] = (p < 5) ? cW2[m * 5 + p] : 0.f;
    }
    if (tid < 64) { sB1[tid] = cB1[tid]; sGb[tid] = gat_b[tid]; }
    if (tid < 8)  sB2[tid] = (tid < 5) ? cB2[tid] : 0.f;
    __syncthreads();

    const int bn = blockIdx.x * 128 + tid;
    const int b  = bn / Nq;
    const int n  = bn % Nq;
    const int base = b * Nq;

    float ad_i = g_ad[bn];
    int   mi   = g_mask[bn];

    float w[5];
    float amax = -1e30f;
    #pragma unroll
    for (int j = 0; j < 5; j++) {
        int src = base + j;
        float a = g_as[src] + ad_i;
        a = a > 0.f ? a : 0.2f * a;
        bool valid = (j == n) ? true : (mi && g_mask[src]);
        w[j] = valid ? a : -1e30f;
        amax = fmaxf(amax, w[j]);
    }
    float denom = 0.f;
    #pragma unroll
    for (int j = 0; j < 5; j++) {
        float e = __expf(w[j] - amax);
        w[j] = e;
        denom += e;
    }
    float inv = __fdividef(1.f, denom);
    #pragma unroll
    for (int j = 0; j < 5; j++) w[j] *= inv;

    u64 acc2[32];
    #pragma unroll
    for (int k = 0; k < 32; k++) acc2[k] = 0ULL;
    #pragma unroll
    for (int j = 0; j < 5; j++) {
        const u64* xr = reinterpret_cast<const u64*>(g_xl) + (size_t)(base + j) * 32;
        u64 wj = bc2(w[j]);
        #pragma unroll
        for (int k = 0; k < 32; k++) acc2[k] = fma2(wj, xr[k], acc2[k]);
    }

    u64 hfp[32];
    const u64* he = reinterpret_cast<const u64*>(g_henc) + (size_t)bn * 32;
    const u64* gb = (const u64*)sGb;
    u64* hfo = reinterpret_cast<u64*>(g_hfin) + (size_t)bn * 32;
    #pragma unroll
    for (int k = 0; k < 32; k++) {
        u64 r = add2(add2(he[k], acc2[k]), gb[k]);
        hfp[k] = r;
        hfo[k] = r;
    }

    u64 o2p[3];
    o2p[0] = pk(sB2[0], sB2[1]);
    o2p[1] = pk(sB2[2], sB2[3]);
    o2p[2] = pk(sB2[4], 0.f);
    #pragma unroll 2
    for (int m = 0; m < 64; m++) {
        const ulonglong2* w1 = (const ulonglong2*)(sW1t + m * 64);
        u64 acc = 0;
        #pragma unroll
        for (int k4 = 0; k4 < 16; k4++) {
            ulonglong2 wv = w1[k4];
            acc = fma2(wv.x, hfp[2 * k4], acc);
            acc = fma2(wv.y, hfp[2 * k4 + 1], acc);
        }
        float t = fmaxf(hadd(acc) + sB1[m], 0.f);
        u64 t2 = bc2(t);
        const u64* w2r = (const u64*)(sW2 + m * 8);
        o2p[0] = fma2(t2, w2r[0], o2p[0]);
        o2p[1] = fma2(t2, w2r[1], o2p[1]);
        o2p[2] = fma2(t2, w2r[2], o2p[2]);
    }
    float o[5];
    { float2 a = unpk(o2p[0]); o[0] = a.x; o[1] = a.y; }
    { float2 a = unpk(o2p[1]); o[2] = a.x; o[3] = a.y; }
    { float2 a = unpk(o2p[2]); o[4] = a.x; }
    float mx = o[0];
    #pragma unroll
    for (int p = 1; p < 5; p++) mx = fmaxf(mx, o[p]);
    float s = 0.f;
    #pragma unroll
    for (int p = 0; p < 5; p++) { o[p] = __expf(o[p] - mx); s += o[p]; }
    float invs = __fdividef(1.f, s);

    float* conf = out + TRAJ_ELEMS;
    #pragma unroll
    for (int p = 0; p < 5; p++)
        conf[(size_t)b * 25 + p * 5 + n] = o[p] * invs;
}

// ------------------------- decoder ------------------------------------------
// 512 threads, 1 node/thread, persistent over tiles of 512 nodes.
// smem floats:
//  sWhh 12288 | sBhh 192 | sWcd 384 | sBcd 192 | sW1t 4096 | sB1 64 |
//  sW2p 768 (stride 12) | sB2 16 | hs 32*512 u64
constexpr int D_WHH = 0;
constexpr int D_BHH = 12288;
constexpr int D_WCD = 12480;
constexpr int D_BCD = 12864;
constexpr int D_W1T = 13056;
constexpr int D_B1  = 17152;
constexpr int D_W2  = 17216;
constexpr int D_B2  = 17984;
constexpr int D_HS  = 18000;
constexpr int DEC_SMEM_FLOATS = D_HS + 32 * 512 * 2;   // 50768
constexpr int DEC_SMEM_BYTES  = DEC_SMEM_FLOATS * 4;   // 203072

__global__ void __launch_bounds__(512, 1) dec_kernel(
    const float* __restrict__ x,
    const float* __restrict__ Whh,
    const float* __restrict__ bhh,
    const float* __restrict__ oW1,
    const float* __restrict__ oB1,
    const float* __restrict__ oW2,
    const float* __restrict__ oB2,
    float* __restrict__ out)
{
    extern __shared__ float sm[];
    float* sWhh = sm + D_WHH;
    float* sBhh = sm + D_BHH;
    float* sWcd = sm + D_WCD;
    float* sBcd = sm + D_BCD;
    float* sW1t = sm + D_W1T;
    float* sB1  = sm + D_B1;
    float* sW2p = sm + D_W2;
    float* sB2  = sm + D_B2;
    u64*   hsu  = reinterpret_cast<u64*>(sm + D_HS);

    const int tid = threadIdx.x;
    for (int i = tid; i < 12288; i += 512) sWhh[i] = Whh[i];
    for (int i = tid; i < 384;   i += 512) sWcd[i] = g_Wc_dec[i];
    for (int i = tid; i < 4096;  i += 512) {
        int m = i >> 6, k = i & 63;
        sW1t[i] = oW1[k * 64 + m];
    }
    for (int i = tid; i < 768;   i += 512) {
        int m = i / 12, c = i % 12;
        sW2p[i] = (c < 10) ? oW2[m * 10 + c] : 0.f;
    }
    if (tid < 192) { sBhh[tid] = bhh[tid]; sBcd[tid] = g_bc_dec[tid]; }
    if (tid < 64) sB1[tid] = oB1[tid];
    if (tid < 16) sB2[tid] = (tid < 10) ? oB2[tid] : 0.f;
    __syncthreads();

    for (int tile = blockIdx.x; tile < TILES; tile += GRID) {

    const int bn = tile * 512 + tid;
    const int b  = bn / Nq;
    const int n  = bn % Nq;

    u64 h2[32];
    {
        const u64* hf = reinterpret_cast<const u64*>(g_hfin) + (size_t)bn * 32;
        #pragma unroll
        for (int k = 0; k < 32; k++) h2[k] = hf[k];
    }

    const float* xl = x + ((size_t)b * (Tq * Nq) + 4 * Nq + n) * Fq;
    u64 xyp = pk(xl[0], xl[1]);

    const u64* wcdp = (const u64*)sWcd;   // pair (w_{j,0}, w_{j,1}) per row j

    for (int t = 0; t < TOq; t++) {
        #pragma unroll 1
        for (int jj = 0; jj < 32; jj++) {
            const int j = 2 * jj;
            const ulonglong2* wh0 = (const ulonglong2*)(sWhh + j * 64);
            const ulonglong2* wh1 = (const ulonglong2*)(sWhh + (j + 1) * 64);
            const ulonglong2* wh2 = (const ulonglong2*)(sWhh + (j + 64) * 64);
            const ulonglong2* wh3 = (const ulonglong2*)(sWhh + (j + 65) * 64);
            const ulonglong2* wh4 = (const ulonglong2*)(sWhh + (j + 128) * 64);
            const ulonglong2* wh5 = (const ulonglong2*)(sWhh + (j + 129) * 64);
            u64 r0 = 0, r1 = 0, z0 = 0, z1 = 0, n0 = 0, n1 = 0;
            #pragma unroll
            for (int k4 = 0; k4 < 16; k4++) {
                u64 ha = h2[2 * k4], hb = h2[2 * k4 + 1];
                ulonglong2 w;
                w = wh0[k4]; r0 = fma2(w.x, ha, r0); r0 = fma2(w.y, hb, r0);
                w = wh1[k4]; r1 = fma2(w.x, ha, r1); r1 = fma2(w.y, hb, r1);
                w = wh2[k4]; z0 = fma2(w.x, ha, z0); z0 = fma2(w.y, hb, z0);
                w = wh3[k4]; z1 = fma2(w.x, ha, z1); z1 = fma2(w.y, hb, z1);
                w = wh4[k4]; n0 = fma2(w.x, ha, n0); n0 = fma2(w.y, hb, n0);
                w = wh5[k4]; n1 = fma2(w.x, ha, n1); n1 = fma2(w.y, hb, n1);
            }
            // x-path: packed 2-wide dot (hadd sums both halves)
            r0 = fma2(wcdp[j],       xyp, r0);
            r1 = fma2(wcdp[j + 1],   xyp, r1);
            z0 = fma2(wcdp[j + 64],  xyp, z0);
            z1 = fma2(wcdp[j + 65],  xyp, z1);
            u64 xn0 = fma2(wcdp[j + 128], xyp, 0ULL);
            u64 xn1 = fma2(wcdp[j + 129], xyp, 0ULL);
            float R0 = sigmf(hadd(r0) + sBcd[j]      + sBhh[j]);
            float R1 = sigmf(hadd(r1) + sBcd[j + 1]  + sBhh[j + 1]);
            float Z0 = sigmf(hadd(z0) + sBcd[j + 64] + sBhh[j + 64]);
            float Z1 = sigmf(hadd(z1) + sBcd[j + 65] + sBhh[j + 65]);
            float N0 = tanhf_(hadd(xn0) + sBcd[j + 128] + R0 * (hadd(n0) + sBhh[j + 128]));
            float N1 = tanhf_(hadd(xn1) + sBcd[j + 129] + R1 * (hadd(n1) + sBhh[j + 129]));
            float2 ho = unpk(h2[jj]);
            hsu[jj * 512 + tid] = pk((1.f - Z0) * N0 + Z0 * ho.x,
                                     (1.f - Z1) * N1 + Z1 * ho.y);
        }
        #pragma unroll
        for (int k = 0; k < 32; k++) h2[k] = hsu[k * 512 + tid];

        // out MLP: o = relu(h @ W1 + b1) @ W2 + b2
        u64 op[5];
        #pragma unroll
        for (int p = 0; p < 5; p++) op[p] = pk(sB2[2 * p], sB2[2 * p + 1]);
        #pragma unroll 2
        for (int m = 0; m < 64; m++) {
            const ulonglong2* w1 = (const ulonglong2*)(sW1t + m * 64);
            u64 acc = 0;
            #pragma unroll
            for (int k4 = 0; k4 < 16; k4++) {
                ulonglong2 wv = w1[k4];
                acc = fma2(wv.x, h2[2 * k4], acc);
                acc = fma2(wv.y, h2[2 * k4 + 1], acc);
            }
            float a = fmaxf(hadd(acc) + sB1[m], 0.f);
            u64 a2 = bc2(a);
            const u64* w2r = (const u64*)(sW2p + m * 12);
            #pragma unroll
            for (int p = 0; p < 5; p++) op[p] = fma2(a2, w2r[p], op[p]);
        }

        float o[10];
        #pragma unroll
        for (int p = 0; p < 5; p++) {
            float2 v = unpk(op[p]);
            o[2 * p] = v.x; o[2 * p + 1] = v.y;
        }

        // traj[b, m, n, t, c] = o[c*5 + m]
        size_t ob = (size_t)b * 300 + (size_t)n * 12 + t * 2;
        #pragma unroll
        for (int m = 0; m < 5; m++) {
            out[ob + m * 60 + 0] = o[m];
            out[ob + m * 60 + 1] = o[5 + m];
        }
        xyp = pk(o[0], o[5]);
    }

    }   // tile loop
}

// ------------------------- launch -------------------------------------------
extern "C" void kernel_launch(void* const* d_in, const int* in_sizes, int n_in,
                              void* d_out, int out_size)
{
    const float* x        = (const float*)d_in[0];
    const float* embW     = (const float*)d_in[1];
    const float* embB     = (const float*)d_in[2];
    const float* gatW     = (const float*)d_in[3];
    const float* attSrc   = (const float*)d_in[4];
    const float* attDst   = (const float*)d_in[5];
    const float* gatB     = (const float*)d_in[6];
    const float* encWih   = (const float*)d_in[7];
    const float* encWhh   = (const float*)d_in[8];
    const float* encBih   = (const float*)d_in[9];
    const float* encBhh   = (const float*)d_in[10];
    const float* decWih   = (const float*)d_in[11];
    const float* decWhh   = (const float*)d_in[12];
    const float* decBih   = (const float*)d_in[13];
    const float* decBhh   = (const float*)d_in[14];
    const float* oW1      = (const float*)d_in[15];
    const float* oB1      = (const float*)d_in[16];
    const float* oW2      = (const float*)d_in[17];
    const float* oB2      = (const float*)d_in[18];
    const float* projW    = (const float*)d_in[19];
    const float* projB    = (const float*)d_in[20];
    const float* cW1      = (const float*)d_in[21];
    const float* cB1      = (const float*)d_in[22];
    const float* cW2      = (const float*)d_in[23];
    const float* cB2      = (const float*)d_in[24];
    float* out = (float*)d_out;

    cudaFuncSetAttribute(enc_kernel, cudaFuncAttributeMaxDynamicSharedMemorySize, ENC_SMEM_BYTES);
    cudaFuncSetAttribute(dec_kernel, cudaFuncAttributeMaxDynamicSharedMemorySize, DEC_SMEM_BYTES);

    prep_kernel<<<27, 128>>>(encWih, encBih, decWih, decBih,
                             embW, embB, projW, projB, gatW);

    enc_kernel<<<GRID, 512, ENC_SMEM_BYTES>>>(x, encWhh, encBhh, attSrc, attDst);

    gat_kernel<<<BNq / 128, 128>>>(gatB, cW1, cB1, cW2, cB2, out);

    dec_kernel<<<GRID, 512, DEC_SMEM_BYTES>>>(x, decWhh, decBhh,
                                              oW1, oB1, oW2, oB2, out);
}